// round 6
// baseline (speedup 1.0000x reference)
#include <cuda_runtime.h>
#include <cuda_bf16.h>
#include <cstdint>

#define NUM_TYPES 3
#define NQ_MAX 500000
#define BSEG_MAX 4000000
#define MAX_TS 10
#define EPS 1e-7f
#define UNROLL 8

// ---------------- device scratch (no allocations allowed) ----------------
__device__ float  g_stats[NUM_TYPES * 3];     // per type: sum, sumsq, cnt
__device__ float2 g_qab[NQ_MAX];              // per question: (A=a_i, B=b_i)
__device__ float2 g_acc[BSEG_MAX];            // per segment: (sum exp(logit), count)
__device__ float  g_exp_ts[MAX_TS + 1];       // exp(team_size_bias)
__device__ int    g_is64;                     // 1 if index arrays are int64

__device__ __forceinline__ int idx_at(const void* p, int i, int is64) {
    return is64 ? (int)((const long long*)p)[i] : ((const int*)p)[i];
}

// ---------------- kernel 0: detect dtype + zero stats + exp(ts_bias) ----------------
__global__ void k_detect(const void* __restrict__ pidx,
                         const float* __restrict__ ts_bias) {
    if (threadIdx.x < NUM_TYPES * 3) g_stats[threadIdx.x] = 0.f;
    if (threadIdx.x < MAX_TS + 1) g_exp_ts[threadIdx.x] = __expf(ts_bias[threadIdx.x]);
    if (threadIdx.x == 0) {
        const int* p32 = (const int*)pidx;
        int any = 0;
        #pragma unroll 8
        for (int k = 0; k < 256; k++) any |= p32[2 * k + 1];
        g_is64 = (any == 0) ? 1 : 0;
    }
}

// ---------------- kernel 1: per-type dl stats ----------------
__global__ void __launch_bounds__(256) k_stats(const float* __restrict__ dl,
                                               const void* __restrict__ type,
                                               int n) {
    const int is64 = g_is64;
    float s[NUM_TYPES]  = {0.f, 0.f, 0.f};
    float s2[NUM_TYPES] = {0.f, 0.f, 0.f};
    float c[NUM_TYPES]  = {0.f, 0.f, 0.f};
    for (int i = blockIdx.x * blockDim.x + threadIdx.x; i < n;
         i += gridDim.x * blockDim.x) {
        int t = idx_at(type, i, is64);
        if (t < 0) t = 0; if (t >= NUM_TYPES) t = NUM_TYPES - 1;
        float v = dl[i];
        s[t]  += v;
        s2[t] += v * v;
        c[t]  += 1.f;
    }
    const unsigned FULL = 0xffffffffu;
    #pragma unroll
    for (int t = 0; t < NUM_TYPES; t++) {
        #pragma unroll
        for (int d = 16; d > 0; d >>= 1) {
            s[t]  += __shfl_down_sync(FULL, s[t], d);
            s2[t] += __shfl_down_sync(FULL, s2[t], d);
            c[t]  += __shfl_down_sync(FULL, c[t], d);
        }
    }
    __shared__ float sh[NUM_TYPES * 3];
    if (threadIdx.x < NUM_TYPES * 3) sh[threadIdx.x] = 0.f;
    __syncthreads();
    if ((threadIdx.x & 31) == 0) {
        #pragma unroll
        for (int t = 0; t < NUM_TYPES; t++) {
            atomicAdd(&sh[t * 3 + 0], s[t]);
            atomicAdd(&sh[t * 3 + 1], s2[t]);
            atomicAdd(&sh[t * 3 + 2], c[t]);
        }
    }
    __syncthreads();
    if (threadIdx.x < NUM_TYPES * 3) atomicAdd(&g_stats[threadIdx.x], sh[threadIdx.x]);
}

// ---------------- kernel 2: per-question A/B precompute + zero g_acc ----------------
__global__ void __launch_bounds__(256) k_question(const float* __restrict__ b,
                                                  const float* __restrict__ log_a,
                                                  const float* __restrict__ dl,
                                                  const void* __restrict__ type,
                                                  const float* __restrict__ dl_scale,
                                                  const float* __restrict__ type_bias,
                                                  int n, int bseg) {
    int i = blockIdx.x * blockDim.x + threadIdx.x;

    // zero 2 float2 accumulator slots (float4 store)
    int j = i * 2;
    if (j + 1 < bseg) {
        *(float4*)&g_acc[j] = make_float4(0.f, 0.f, 0.f, 0.f);
    } else if (j < bseg) {
        g_acc[j] = make_float2(0.f, 0.f);
    }

    if (i >= n) return;
    int t = idx_at(type, i, g_is64);
    if (t < 0) t = 0; if (t >= NUM_TYPES) t = NUM_TYPES - 1;
    float sum  = g_stats[t * 3 + 0];
    float sum2 = g_stats[t * 3 + 1];
    float cnt  = g_stats[t * 3 + 2];
    float sc   = fmaxf(cnt, 1.f);
    float mean = sum / sc;
    float ex2  = sum2 / sc;
    float stdv = sqrtf(fmaxf(ex2 - mean * mean, 0.f));
    mean = (cnt > 0.f) ? mean : 0.f;
    stdv = (cnt > 0.f && stdv > 1e-6f) ? stdv : 1.f;
    float dln = (dl[i] - mean) / stdv;
    float Bv  = b[i] + type_bias[t] + dl_scale[t] * dln;
    float Av  = fmaxf(expf(log_a[i]), EPS);
    g_qab[i]  = make_float2(Av, Bv);
}

// ---------------- kernel 3: main 24M segmented reduction (x8 unrolled) ----------------
__global__ void __launch_bounds__(256) k_main(const float* __restrict__ theta,
                                              const void* __restrict__ qidx,
                                              const void* __restrict__ pidx,
                                              const void* __restrict__ seg,
                                              int total, int nq, int bseg) {
    const unsigned FULL = 0xffffffffu;
    const int is64 = g_is64;
    const int lane = threadIdx.x & 31;
    const int stride = gridDim.x * blockDim.x;
    const int base = blockIdx.x * blockDim.x + threadIdx.x;

    int   s[UNROLL], p[UNROLL], q[UNROLL];
    float v[UNROLL];

    // batch the streaming loads (seg, pidx) for all chunks -> high MLP
    #pragma unroll
    for (int u = 0; u < UNROLL; u++) {
        int i = base + u * stride;
        if (i < total) {
            s[u] = idx_at(seg, i, is64);
            if (s[u] < 0) s[u] = 0; if (s[u] >= bseg) s[u] = bseg - 1;
            p[u] = idx_at(pidx, i, is64);
        } else { s[u] = -1; p[u] = 0; }
    }
    // dependent qidx loads (batched)
    #pragma unroll
    for (int u = 0; u < UNROLL; u++) {
        q[u] = (s[u] >= 0) ? idx_at(qidx, s[u], is64) : 0;
        if (q[u] < 0) q[u] = 0; if (q[u] >= nq) q[u] = nq - 1;
    }
    // qab + theta gathers (batched), then math
    float2 ab[UNROLL];
    float  th[UNROLL];
    #pragma unroll
    for (int u = 0; u < UNROLL; u++) {
        ab[u] = g_qab[q[u]];
        th[u] = __ldg(&theta[p[u]]);
    }
    #pragma unroll
    for (int u = 0; u < UNROLL; u++) {
        float l = fmaf(ab[u].x, th[u], -ab[u].y);
        l = fminf(fmaxf(l, -20.f), 20.f);
        v[u] = (s[u] >= 0) ? __expf(l) : 0.f;
    }

    // per-chunk warp-segmented scan: boundaries via ballot, count via position math
    #pragma unroll
    for (int u = 0; u < UNROLL; u++) {
        int sprev = __shfl_up_sync(FULL, s[u], 1);
        bool newseg = (lane == 0) || (sprev != s[u]);
        unsigned bmask = __ballot_sync(FULL, newseg);
        unsigned lemask = 0xffffffffu >> (31 - lane);
        int head = 31 - __clz(bmask & lemask);   // lane of this run's first elem
        float vv = v[u];
        #pragma unroll
        for (int d = 1; d < 32; d <<= 1) {
            float up = __shfl_up_sync(FULL, vv, d);
            if (lane - d >= head) vv += up;
        }
        bool tail = (lane == 31) || ((bmask >> (lane + 1)) & 1u);
        if (tail && s[u] >= 0) {
            float cnt = (float)(lane - head + 1);
            asm volatile("red.global.add.v2.f32 [%0], {%1, %2};"
                         :: "l"(&g_acc[s[u]]), "f"(vv), "f"(cnt) : "memory");
        }
    }
}

// ---------------- kernel 4: finalize (2 segments / thread, float4 loads) ----------------
__global__ void __launch_bounds__(256) k_final(float* __restrict__ out, int n) {
    int i = blockIdx.x * blockDim.x + threadIdx.x;
    int j = 2 * i;
    if (j >= n) return;
    float4 a = *(const float4*)&g_acc[j];

    int ts0 = (int)a.y; ts0 = (ts0 > MAX_TS) ? MAX_TS : ts0; if (ts0 < 0) ts0 = 0;
    float lam0 = a.x * __ldg(&g_exp_ts[ts0]);
    float p0 = fminf(fmaxf(1.f - __expf(-lam0), EPS), 1.f - EPS);

    if (j + 1 < n) {
        int ts1 = (int)a.w; ts1 = (ts1 > MAX_TS) ? MAX_TS : ts1; if (ts1 < 0) ts1 = 0;
        float lam1 = a.z * __ldg(&g_exp_ts[ts1]);
        float p1 = fminf(fmaxf(1.f - __expf(-lam1), EPS), 1.f - EPS);
        *(float2*)&out[j] = make_float2(p0, p1);
    } else {
        out[j] = p0;
    }
}

// ---------------- launch ----------------
extern "C" void kernel_launch(void* const* d_in, const int* in_sizes, int n_in,
                              void* d_out, int out_size) {
    const float* theta     = (const float*)d_in[0];
    const float* b         = (const float*)d_in[1];
    const float* log_a     = (const float*)d_in[2];
    const float* ts_bias   = (const float*)d_in[3];
    const float* dl_scale  = (const float*)d_in[4];
    const float* type_bias = (const float*)d_in[5];
    const float* dl        = (const float*)d_in[6];
    const void*  ttype     = (const void*)d_in[7];
    const void*  qidx      = (const void*)d_in[8];
    const void*  pidx      = (const void*)d_in[9];
    const void*  seg       = (const void*)d_in[10];
    float*       out       = (float*)d_out;

    int nq    = in_sizes[6];
    int bseg  = out_size;
    int total = in_sizes[9];
    if (nq > NQ_MAX) nq = NQ_MAX;
    if (bseg > BSEG_MAX) bseg = BSEG_MAX;

    k_detect<<<1, 32>>>(pidx, ts_bias);
    k_stats<<<512, 256>>>(dl, ttype, nq);

    // k_question also zeroes g_acc: needs max(nq, ceil(bseg/2)) threads
    int qz = nq > (bseg + 1) / 2 ? nq : (bseg + 1) / 2;
    k_question<<<(qz + 255) / 256, 256>>>(b, log_a, dl, ttype, dl_scale, type_bias,
                                          nq, bseg);

    int per_blk = 256 * UNROLL;
    int grid = (total + per_blk - 1) / per_blk;
    k_main<<<grid, 256>>>(theta, qidx, pidx, seg, total, nq, bseg);

    k_final<<<(bseg / 2 + 255) / 256, 256>>>(out, bseg);
}

// round 7
// speedup vs baseline: 1.2664x; 1.2664x over previous
#include <cuda_runtime.h>
#include <cuda_bf16.h>
#include <cstdint>

#define NUM_TYPES 3
#define NQ_MAX 500000
#define BSEG_MAX 4000000
#define MAX_TS 10
#define EPS 1e-7f
#define UNROLL 4

// ---------------- device scratch (no allocations allowed) ----------------
__device__ float  g_stats[NUM_TYPES * 3];     // per type: sum, sumsq, cnt
__device__ float2 g_qab[NQ_MAX];              // per question: (A=a_i, B=b_i)
__device__ float2 g_acc[BSEG_MAX];            // per segment: (sum exp(logit), count)
__device__ float  g_exp_ts[MAX_TS + 1];       // exp(team_size_bias)
__device__ int    g_is64;                     // 1 if index arrays are int64

__device__ __forceinline__ int idx_at(const void* p, int i, int is64) {
    return is64 ? (int)((const long long*)p)[i] : ((const int*)p)[i];
}

// ---------------- kernel 0: detect dtype + zero stats + exp(ts_bias) ----------------
__global__ void k_detect(const void* __restrict__ pidx,
                         const float* __restrict__ ts_bias) {
    if (threadIdx.x < NUM_TYPES * 3) g_stats[threadIdx.x] = 0.f;
    if (threadIdx.x < MAX_TS + 1) g_exp_ts[threadIdx.x] = __expf(ts_bias[threadIdx.x]);
    if (threadIdx.x == 0) {
        const int* p32 = (const int*)pidx;
        int any = 0;
        #pragma unroll 8
        for (int k = 0; k < 256; k++) any |= p32[2 * k + 1];
        g_is64 = (any == 0) ? 1 : 0;
    }
}

// ---------------- kernel 1: per-type dl stats ----------------
__global__ void __launch_bounds__(256) k_stats(const float* __restrict__ dl,
                                               const void* __restrict__ type,
                                               int n) {
    const int is64 = g_is64;
    float s[NUM_TYPES]  = {0.f, 0.f, 0.f};
    float s2[NUM_TYPES] = {0.f, 0.f, 0.f};
    float c[NUM_TYPES]  = {0.f, 0.f, 0.f};
    for (int i = blockIdx.x * blockDim.x + threadIdx.x; i < n;
         i += gridDim.x * blockDim.x) {
        int t = idx_at(type, i, is64);
        if (t < 0) t = 0; if (t >= NUM_TYPES) t = NUM_TYPES - 1;
        float v = dl[i];
        s[t]  += v;
        s2[t] += v * v;
        c[t]  += 1.f;
    }
    const unsigned FULL = 0xffffffffu;
    #pragma unroll
    for (int t = 0; t < NUM_TYPES; t++) {
        #pragma unroll
        for (int d = 16; d > 0; d >>= 1) {
            s[t]  += __shfl_down_sync(FULL, s[t], d);
            s2[t] += __shfl_down_sync(FULL, s2[t], d);
            c[t]  += __shfl_down_sync(FULL, c[t], d);
        }
    }
    __shared__ float sh[NUM_TYPES * 3];
    if (threadIdx.x < NUM_TYPES * 3) sh[threadIdx.x] = 0.f;
    __syncthreads();
    if ((threadIdx.x & 31) == 0) {
        #pragma unroll
        for (int t = 0; t < NUM_TYPES; t++) {
            atomicAdd(&sh[t * 3 + 0], s[t]);
            atomicAdd(&sh[t * 3 + 1], s2[t]);
            atomicAdd(&sh[t * 3 + 2], c[t]);
        }
    }
    __syncthreads();
    if (threadIdx.x < NUM_TYPES * 3) atomicAdd(&g_stats[threadIdx.x], sh[threadIdx.x]);
}

// ---------------- kernel 2: per-question A/B precompute + zero g_acc ----------------
__global__ void __launch_bounds__(256) k_question(const float* __restrict__ b,
                                                  const float* __restrict__ log_a,
                                                  const float* __restrict__ dl,
                                                  const void* __restrict__ type,
                                                  const float* __restrict__ dl_scale,
                                                  const float* __restrict__ type_bias,
                                                  int n, int bseg) {
    int i = blockIdx.x * blockDim.x + threadIdx.x;

    // zero 2 float2 accumulator slots (float4 store)
    int j = i * 2;
    if (j + 1 < bseg) {
        *(float4*)&g_acc[j] = make_float4(0.f, 0.f, 0.f, 0.f);
    } else if (j < bseg) {
        g_acc[j] = make_float2(0.f, 0.f);
    }

    if (i >= n) return;
    int t = idx_at(type, i, g_is64);
    if (t < 0) t = 0; if (t >= NUM_TYPES) t = NUM_TYPES - 1;
    float sum  = g_stats[t * 3 + 0];
    float sum2 = g_stats[t * 3 + 1];
    float cnt  = g_stats[t * 3 + 2];
    float sc   = fmaxf(cnt, 1.f);
    float mean = sum / sc;
    float ex2  = sum2 / sc;
    float stdv = sqrtf(fmaxf(ex2 - mean * mean, 0.f));
    mean = (cnt > 0.f) ? mean : 0.f;
    stdv = (cnt > 0.f && stdv > 1e-6f) ? stdv : 1.f;
    float dln = (dl[i] - mean) / stdv;
    float Bv  = b[i] + type_bias[t] + dl_scale[t] * dln;
    float Av  = fmaxf(expf(log_a[i]), EPS);
    g_qab[i]  = make_float2(Av, Bv);
}

// ---------------- kernel 3: main 24M segmented reduction (x4, theta-first) ----------------
__global__ void __launch_bounds__(256) k_main(const float* __restrict__ theta,
                                              const void* __restrict__ qidx,
                                              const void* __restrict__ pidx,
                                              const void* __restrict__ seg,
                                              int total, int nq, int bseg) {
    const unsigned FULL = 0xffffffffu;
    const int is64 = g_is64;
    const int lane = threadIdx.x & 31;
    const int stride = gridDim.x * blockDim.x;
    const int base = blockIdx.x * blockDim.x + threadIdx.x;

    int   s[UNROLL], p[UNROLL], q[UNROLL];
    float v[UNROLL], th[UNROLL];
    float2 ab[UNROLL];

    // phase 1: streaming loads (seg, pidx)
    #pragma unroll
    for (int u = 0; u < UNROLL; u++) {
        int i = base + u * stride;
        if (i < total) {
            s[u] = idx_at(seg, i, is64);
            p[u] = idx_at(pidx, i, is64);
        } else { s[u] = -1; p[u] = 0; }
    }
    // phase 2: theta gathers FIRST (long pole; depends only on pidx)
    #pragma unroll
    for (int u = 0; u < UNROLL; u++) th[u] = __ldg(&theta[p[u]]);
    // phase 3: qidx gathers (dependent chain hop 1)
    #pragma unroll
    for (int u = 0; u < UNROLL; u++)
        q[u] = (s[u] >= 0) ? idx_at(qidx, s[u], is64) : 0;
    // phase 4: qab gathers (hop 2)
    #pragma unroll
    for (int u = 0; u < UNROLL; u++) ab[u] = g_qab[q[u]];
    // math
    #pragma unroll
    for (int u = 0; u < UNROLL; u++) {
        float l = fmaf(ab[u].x, th[u], -ab[u].y);
        l = fminf(fmaxf(l, -20.f), 20.f);
        v[u] = (s[u] >= 0) ? __expf(l) : 0.f;
    }

    // per-chunk warp-segmented scan: boundaries via ballot, count via position math
    #pragma unroll
    for (int u = 0; u < UNROLL; u++) {
        int sprev = __shfl_up_sync(FULL, s[u], 1);
        bool newseg = (lane == 0) || (sprev != s[u]);
        unsigned bmask = __ballot_sync(FULL, newseg);
        unsigned lemask = 0xffffffffu >> (31 - lane);
        int head = 31 - __clz(bmask & lemask);   // lane of this run's first elem
        float vv = v[u];
        #pragma unroll
        for (int d = 1; d < 32; d <<= 1) {
            float up = __shfl_up_sync(FULL, vv, d);
            if (lane - d >= head) vv += up;
        }
        bool tail = (lane == 31) || ((bmask >> (lane + 1)) & 1u);
        if (tail && s[u] >= 0) {
            float cnt = (float)(lane - head + 1);
            asm volatile("red.global.add.v2.f32 [%0], {%1, %2};"
                         :: "l"(&g_acc[s[u]]), "f"(vv), "f"(cnt) : "memory");
        }
    }
}

// ---------------- kernel 4: finalize (2 segments / thread, float4 loads) ----------------
__global__ void __launch_bounds__(256) k_final(float* __restrict__ out, int n) {
    int i = blockIdx.x * blockDim.x + threadIdx.x;
    int j = 2 * i;
    if (j >= n) return;
    float4 a = *(const float4*)&g_acc[j];

    int ts0 = (int)a.y; ts0 = (ts0 > MAX_TS) ? MAX_TS : ts0; if (ts0 < 0) ts0 = 0;
    float lam0 = a.x * __ldg(&g_exp_ts[ts0]);
    float p0 = fminf(fmaxf(1.f - __expf(-lam0), EPS), 1.f - EPS);

    if (j + 1 < n) {
        int ts1 = (int)a.w; ts1 = (ts1 > MAX_TS) ? MAX_TS : ts1; if (ts1 < 0) ts1 = 0;
        float lam1 = a.z * __ldg(&g_exp_ts[ts1]);
        float p1 = fminf(fmaxf(1.f - __expf(-lam1), EPS), 1.f - EPS);
        *(float2*)&out[j] = make_float2(p0, p1);
    } else {
        out[j] = p0;
    }
}

// ---------------- launch ----------------
extern "C" void kernel_launch(void* const* d_in, const int* in_sizes, int n_in,
                              void* d_out, int out_size) {
    const float* theta     = (const float*)d_in[0];
    const float* b         = (const float*)d_in[1];
    const float* log_a     = (const float*)d_in[2];
    const float* ts_bias   = (const float*)d_in[3];
    const float* dl_scale  = (const float*)d_in[4];
    const float* type_bias = (const float*)d_in[5];
    const float* dl        = (const float*)d_in[6];
    const void*  ttype     = (const void*)d_in[7];
    const void*  qidx      = (const void*)d_in[8];
    const void*  pidx      = (const void*)d_in[9];
    const void*  seg       = (const void*)d_in[10];
    float*       out       = (float*)d_out;

    int nq    = in_sizes[6];
    int bseg  = out_size;
    int total = in_sizes[9];
    if (nq > NQ_MAX) nq = NQ_MAX;
    if (bseg > BSEG_MAX) bseg = BSEG_MAX;

    k_detect<<<1, 32>>>(pidx, ts_bias);
    k_stats<<<512, 256>>>(dl, ttype, nq);

    // k_question also zeroes g_acc: needs max(nq, ceil(bseg/2)) threads
    int qz = nq > (bseg + 1) / 2 ? nq : (bseg + 1) / 2;
    k_question<<<(qz + 255) / 256, 256>>>(b, log_a, dl, ttype, dl_scale, type_bias,
                                          nq, bseg);

    int per_blk = 256 * UNROLL;
    int grid = (total + per_blk - 1) / per_blk;
    k_main<<<grid, 256>>>(theta, qidx, pidx, seg, total, nq, bseg);

    k_final<<<(bseg / 2 + 255) / 256, 256>>>(out, bseg);
}